// round 4
// baseline (speedup 1.0000x reference)
#include <cuda_runtime.h>
#include <cuda_bf16.h>
#include <math_constants.h>

// ----------------------------------------------------------------------------
// MinArcSoftmaxLoss — 2 kernels: work-stealing streaming + tiny finalize.
//   theta = acos(costh); pos = theta[r,label]; mean/std (ddof=1)
//   d = mean + std*eps (0 at label); mm = cos(theta-d); pm = cos(theta+M@label)
//   logits = S*(A*mm + pm)/(1+A); loss = -mean(log_softmax[label])
// Off-label: mm = c*cos(d) + sqrt(1-c^2)*sin(d), pm = c  → acos-free streaming.
// Fixed softmax shift of 64 (>= all logits).
// Every streaming block computes mean/std redundantly (bit-identical across
// blocks, ~1us latency-bound, overlapped). Block 0 also writes per-row fixup.
// Tiles are claimed via a global ticket counter; finalize resets it to 0 so
// graph replays see a fresh counter. Tile->partial mapping is static, so the
// result is deterministic regardless of claim order.
// ----------------------------------------------------------------------------

#define BQ      512
#define NSPLIT  25                  // 100000/25 = 4000 elems/tile (%4==0)
#define NT      (BQ * NSPLIT)       // 12800 tiles
#define GRID    1184
#define NTHR    256

__device__ unsigned g_tick = 0;     // work-stealing ticket; finalize resets
__device__ float g_fix[BQ];         // pr - pw per row
__device__ float g_logit[BQ];       // correct label logit per row
__device__ float g_partial[NT];

#define K1F   ((float)(64.0 * 0.1 / 1.1))                      // S*A/(1+A)
#define K2F   ((float)(64.0 / 1.1))                            // S/(1+A)
#define L1F   ((float)(64.0 * 0.1 / 1.1 * 1.4426950408889634)) // K1*log2(e)
#define L2F   ((float)(64.0 / 1.1 * 1.4426950408889634))       // K2*log2(e)
#define LOG2E 1.4426950408889634f
#define BIASF ((float)(64.0 * 1.4426950408889634))             // 64*log2(e)
#define COSM  0.8775825618903728f                              // cos(0.5)
#define SINM  0.479425538604203f                               // sin(0.5)

__device__ __forceinline__ float fast_sin(float x) {
    float r; asm("sin.approx.ftz.f32 %0, %1;" : "=f"(r) : "f"(x)); return r;
}
__device__ __forceinline__ float fast_cos(float x) {
    float r; asm("cos.approx.ftz.f32 %0, %1;" : "=f"(r) : "f"(x)); return r;
}
__device__ __forceinline__ float fast_ex2(float x) {
    float r; asm("ex2.approx.ftz.f32 %0, %1;" : "=f"(r) : "f"(x)); return r;
}
__device__ __forceinline__ float fast_rsqrt(float x) {
    float r; asm("rsqrt.approx.ftz.f32 %0, %1;" : "=f"(r) : "f"(x)); return r;
}

// acos via Hastings poly, abs err ~6.8e-5 (fine vs 1e-3 tolerance)
__device__ __forceinline__ float facos(float x) {
    float u = fabsf(x);
    float t = sqrtf(1.0f - u);
    float p = fmaf(u, fmaf(u, fmaf(u, -0.0187292994f, 0.0742610037f),
                           -0.2121144025f), 1.5707288f);
    p *= t;
    return (x >= 0.0f) ? p : ((float)M_PI - p);
}

// exp(logit - 64) via the off-label formula (identical in stream + fixup)
__device__ __forceinline__ float term(float c, float e, float mean, float stdv) {
    float d  = fmaf(e, stdv, mean);
    float sd = fast_sin(d);
    float cd = fast_cos(d);
    float s2 = fmaf(-c, c, 1.0f);            // 1 - c^2 (>= 0.0199)
    float s  = s2 * fast_rsqrt(s2);          // sqrt(1-c^2)
    float mm = fmaf(s, sd, c * cd);          // cos(theta - d)
    return fast_ex2(fmaf(L1F, mm, fmaf(L2F, c, -BIASF)));
}

// block-wide sum over 256 threads, result broadcast
__device__ __forceinline__ float blockSum256(float v, float* sh) {
    #pragma unroll
    for (int o = 16; o; o >>= 1) v += __shfl_down_sync(0xffffffffu, v, o);
    if ((threadIdx.x & 31) == 0) sh[threadIdx.x >> 5] = v;
    __syncthreads();
    if (threadIdx.x < 32) {
        float x = (threadIdx.x < 8) ? sh[threadIdx.x] : 0.0f;
        #pragma unroll
        for (int o = 4; o; o >>= 1) x += __shfl_down_sync(0xffffffffu, x, o);
        if (threadIdx.x == 0) sh[0] = x;
    }
    __syncthreads();
    float r = sh[0];
    __syncthreads();
    return r;
}

__global__ void main_kernel(const float* __restrict__ costh,
                            const float* __restrict__ eps,
                            const int*   __restrict__ lab32,
                            int C) {
    __shared__ float sh[8];
    __shared__ unsigned s_tile;
    int tid = threadIdx.x;

    // ---------- per-block redundant stats (bit-identical everywhere) --------
    int r0 = tid, r1 = tid + 256;
    // dtype detect: int64 labels (<1e5) have all-zero odd int32 slots
    int odd = lab32[2 * r0 + 1] | lab32[2 * r1 + 1];
    int any = __syncthreads_or(odd);
    bool is64 = (any == 0);
    int l0 = is64 ? lab32[2 * r0] : lab32[r0];
    int l1 = is64 ? lab32[2 * r1] : lab32[r1];
    size_t i0 = (size_t)r0 * C + (size_t)l0;
    size_t i1 = (size_t)r1 * C + (size_t)l1;
    float c0 = __ldg(costh + i0);
    float c1 = __ldg(costh + i1);
    float th0 = facos(c0), th1 = facos(c1);
    float mean = blockSum256(th0 + th1, sh) * (1.0f / (float)BQ);
    float d0 = th0 - mean, d1 = th1 - mean;
    float var = blockSum256(fmaf(d0, d0, d1 * d1), sh) * (1.0f / (float)(BQ - 1));
    float stdv = sqrtf(var);

    // ---------- block 0 only: per-row label fixup ----------------------------
    if (blockIdx.x == 0) {
        float e0 = __ldg(eps + i0);
        float e1 = __ldg(eps + i1);
        #pragma unroll
        for (int k = 0; k < 2; k++) {
            int   r  = k ? r1 : r0;
            float cl = k ? c1 : c0;
            float el = k ? e1 : e0;
            float pw = term(cl, el, mean, stdv);
            float s2 = fmaf(-cl, cl, 1.0f);
            float sl = sqrtf(s2);
            float logit_r = fmaf(K1F, cl, K2F * fmaf(cl, COSM, -sl * SINM));
            float pr = fast_ex2(fmaf(logit_r, LOG2E, -BIASF));
            g_fix[r]   = pr - pw;
            g_logit[r] = logit_r;
        }
    }

    // ---------- work-stealing streaming loop ---------------------------------
    int chunk = C / NSPLIT;                  // 4000
    int nvec  = chunk >> 2;                  // 1000 float4s
    for (;;) {
        if (tid == 0) s_tile = atomicAdd(&g_tick, 1u);
        __syncthreads();
        unsigned tile = s_tile;
        __syncthreads();
        if (tile >= NT) break;

        int row   = (int)(tile / NSPLIT);
        int split = (int)(tile % NSPLIT);
        size_t base = (size_t)row * C + (size_t)split * chunk;
        const float4* __restrict__ c4 = (const float4*)(costh + base);
        const float4* __restrict__ e4 = (const float4*)(eps + base);

        float acc = 0.0f;
        for (int i = tid; i < nvec; i += NTHR) {
            float4 c = c4[i];
            float4 e = e4[i];
            acc += term(c.x, e.x, mean, stdv);
            acc += term(c.y, e.y, mean, stdv);
            acc += term(c.z, e.z, mean, stdv);
            acc += term(c.w, e.w, mean, stdv);
        }
        #pragma unroll
        for (int o = 16; o; o >>= 1) acc += __shfl_down_sync(0xffffffffu, acc, o);
        if ((tid & 31) == 0) sh[tid >> 5] = acc;
        __syncthreads();
        if (tid < 32) {
            float v = (tid < 8) ? sh[tid] : 0.0f;
            #pragma unroll
            for (int o = 4; o; o >>= 1) v += __shfl_down_sync(0xffffffffu, v, o);
            if (tid == 0) g_partial[tile] = v;
        }
        __syncthreads();
    }
}

// ---------------- finalize: row losses + mean, reset ticket ------------------
__global__ void finalize_kernel(float* __restrict__ out) {
    __shared__ float sh[BQ];
    int r = threadIdx.x;
    float s = 0.0f;
    #pragma unroll
    for (int j = 0; j < NSPLIT; j++) s += g_partial[r * NSPLIT + j];
    s += g_fix[r];
    float loss = 64.0f + logf(s) - g_logit[r];   // -logp[label]
    sh[r] = loss;
    __syncthreads();
    #pragma unroll
    for (int k = BQ / 2; k > 0; k >>= 1) {
        if (r < k) sh[r] += sh[r + k];
        __syncthreads();
    }
    if (r == 0) {
        out[0] = sh[0] / (float)BQ;
        g_tick = 0;                  // fresh ticket counter for next replay
    }
}

// ----------------------------------------------------------------------------
extern "C" void kernel_launch(void* const* d_in, const int* in_sizes, int n_in,
                              void* d_out, int out_size) {
    const float* costh = (const float*)d_in[0];
    const float* eps   = (const float*)d_in[1];
    const int*   lab32 = (const int*)d_in[2];
    int C = in_sizes[0] / BQ;        // 100000

    main_kernel<<<GRID, NTHR>>>(costh, eps, lab32, C);
    finalize_kernel<<<1, BQ>>>((float*)d_out);
}

// round 5
// speedup vs baseline: 1.0909x; 1.0909x over previous
#include <cuda_runtime.h>
#include <cuda_bf16.h>
#include <math_constants.h>

// ----------------------------------------------------------------------------
// MinArcSoftmaxLoss — stats kernel + streaming kernel with fused finalize.
//   theta = acos(costh); pos = theta[r,label]; mean/std (ddof=1)
//   d = mean + std*eps (0 at label); mm = cos(theta-d); pm = cos(theta+M@label)
//   logits = S*(A*mm + pm)/(1+A); loss = -mean(log_softmax[label])
// Off-label: mm = c*cos(d) + sqrt(1-c^2)*sin(d), pm = c  → acos-free streaming.
// Fixed softmax shift of 64 (>= all logits).
// Finalize runs in the LAST streaming block (done-counter); counter is reset
// there so graph replays start fresh. Fixed tile->partial map => deterministic.
// ----------------------------------------------------------------------------

#define BQ      512
#define NSPLIT  4
#define GRID    (BQ * NSPLIT)       // 2048 blocks, 25000 elems each
#define NTHR    256

__device__ unsigned g_done = 0;
__device__ float g_mean, g_std;
__device__ float g_fix[BQ];         // pr - pw per row
__device__ float g_logit[BQ];       // correct label logit per row
__device__ float g_partial[GRID];

#define K1F   ((float)(64.0 * 0.1 / 1.1))                      // S*A/(1+A)
#define K2F   ((float)(64.0 / 1.1))                            // S/(1+A)
#define L1F   ((float)(64.0 * 0.1 / 1.1 * 1.4426950408889634)) // K1*log2(e)
#define L2F   ((float)(64.0 / 1.1 * 1.4426950408889634))       // K2*log2(e)
#define LOG2E 1.4426950408889634f
#define BIASF ((float)(64.0 * 1.4426950408889634))             // 64*log2(e)
#define COSM  0.8775825618903728f                              // cos(0.5)
#define SINM  0.479425538604203f                               // sin(0.5)

__device__ __forceinline__ float fast_sin(float x) {
    float r; asm("sin.approx.ftz.f32 %0, %1;" : "=f"(r) : "f"(x)); return r;
}
__device__ __forceinline__ float fast_cos(float x) {
    float r; asm("cos.approx.ftz.f32 %0, %1;" : "=f"(r) : "f"(x)); return r;
}
__device__ __forceinline__ float fast_ex2(float x) {
    float r; asm("ex2.approx.ftz.f32 %0, %1;" : "=f"(r) : "f"(x)); return r;
}
__device__ __forceinline__ float fast_rsqrt(float x) {
    float r; asm("rsqrt.approx.ftz.f32 %0, %1;" : "=f"(r) : "f"(x)); return r;
}

// acos via Hastings poly, abs err ~6.8e-5 (fine vs 1e-3 tolerance)
__device__ __forceinline__ float facos(float x) {
    float u = fabsf(x);
    float t = sqrtf(1.0f - u);
    float p = fmaf(u, fmaf(u, fmaf(u, -0.0187292994f, 0.0742610037f),
                           -0.2121144025f), 1.5707288f);
    p *= t;
    return (x >= 0.0f) ? p : ((float)M_PI - p);
}

// exp(logit - 64) via the off-label formula (identical in stream + fixup)
__device__ __forceinline__ float term(float c, float e, float mean, float stdv) {
    float d  = fmaf(e, stdv, mean);
    float sd = fast_sin(d);
    float cd = fast_cos(d);
    float s2 = fmaf(-c, c, 1.0f);            // 1 - c^2 (>= 0.0199)
    float s  = s2 * fast_rsqrt(s2);          // sqrt(1-c^2)
    float mm = fmaf(s, sd, c * cd);          // cos(theta - d)
    return fast_ex2(fmaf(L1F, mm, fmaf(L2F, c, -BIASF)));
}

// sum over 512 threads via shuffles + one smem pass; result broadcast via smem
__device__ __forceinline__ float blockSum512(float v, volatile float* sh16) {
    #pragma unroll
    for (int o = 16; o; o >>= 1) v += __shfl_down_sync(0xffffffffu, v, o);
    if ((threadIdx.x & 31) == 0) sh16[threadIdx.x >> 5] = v;
    __syncthreads();
    if (threadIdx.x < 32) {
        float x = (threadIdx.x < 16) ? sh16[threadIdx.x] : 0.0f;
        #pragma unroll
        for (int o = 8; o; o >>= 1) x += __shfl_down_sync(0xffffffffu, x, o);
        if (threadIdx.x == 0) sh16[0] = x;
    }
    __syncthreads();
    float r = sh16[0];
    __syncthreads();
    return r;
}

// ---------------- kernel 1: dtype detect + mean/std + per-row fixup ---------
__global__ void __launch_bounds__(BQ) stats_kernel(const float* __restrict__ costh,
                                                   const float* __restrict__ eps,
                                                   const int* __restrict__ lab32,
                                                   int C) {
    __shared__ float sh16[16];
    int r = threadIdx.x;
    // dtype detect: int64 labels (<1e5) have all-zero odd int32 slots
    int odd = lab32[2 * r + 1];
    int any = __syncthreads_or(odd);
    int lab = (any == 0) ? lab32[2 * r] : lab32[r];
    size_t idx = (size_t)r * C + (size_t)lab;
    float cl = __ldg(costh + idx);
    float el = __ldg(eps + idx);

    float theta = facos(cl);
    float mean = blockSum512(theta, sh16) * (1.0f / (float)BQ);
    float dev = theta - mean;
    float var = blockSum512(dev * dev, sh16) * (1.0f / (float)(BQ - 1));
    float stdv = sqrtf(var);

    // per-row fixup: remove wrong-formula term, add correct label term
    float pw = term(cl, el, mean, stdv);
    float s2 = fmaf(-cl, cl, 1.0f);
    float sl = sqrtf(s2);
    float logit_r = fmaf(K1F, cl, K2F * fmaf(cl, COSM, -sl * SINM));
    float pr = fast_ex2(fmaf(logit_r, LOG2E, -BIASF));
    g_fix[r]   = pr - pw;
    g_logit[r] = logit_r;
    if (r == 0) { g_mean = mean; g_std = stdv; }
}

// ---------------- kernel 2: streaming exp-sums + fused finalize --------------
__global__ void __launch_bounds__(NTHR) main_kernel(const float* __restrict__ costh,
                                                    const float* __restrict__ eps,
                                                    float* __restrict__ out,
                                                    int C) {
    __shared__ float sh[8];
    int tid = threadIdx.x;
    int row   = blockIdx.x >> 2;
    int split = blockIdx.x & 3;
    int chunk = C / NSPLIT;                  // 25000 (%4 == 0)
    int nvec  = chunk >> 2;                  // 6250 float4s
    size_t base = (size_t)row * C + (size_t)split * chunk;
    const float4* __restrict__ c4 = (const float4*)(costh + base);
    const float4* __restrict__ e4 = (const float4*)(eps + base);

    float mean = g_mean, stdv = g_std;
    float acc = 0.0f;
    #pragma unroll 2
    for (int i = tid; i < nvec; i += NTHR) {
        float4 c = __ldcs(c4 + i);
        float4 e = __ldcs(e4 + i);
        acc += term(c.x, e.x, mean, stdv);
        acc += term(c.y, e.y, mean, stdv);
        acc += term(c.z, e.z, mean, stdv);
        acc += term(c.w, e.w, mean, stdv);
    }
    #pragma unroll
    for (int o = 16; o; o >>= 1) acc += __shfl_down_sync(0xffffffffu, acc, o);
    if ((tid & 31) == 0) sh[tid >> 5] = acc;
    __syncthreads();
    if (tid < 32) {
        float v = (tid < 8) ? sh[tid] : 0.0f;
        #pragma unroll
        for (int o = 4; o; o >>= 1) v += __shfl_down_sync(0xffffffffu, v, o);
        if (tid == 0) sh[0] = v;
    }
    __syncthreads();

    // publish partial, then count completion
    __shared__ bool s_last;
    if (tid == 0) {
        g_partial[blockIdx.x] = sh[0];
        __threadfence();
        unsigned d = atomicAdd(&g_done, 1u);
        s_last = (d == GRID - 1u);
    }
    __syncthreads();
    if (!s_last) return;

    // -------- fused finalize (last block only) --------
    __threadfence();                         // acquire all partials/fixups
    float lsum = 0.0f;
    for (int r = tid; r < BQ; r += NTHR) {
        float s = 0.0f;
        #pragma unroll
        for (int j = 0; j < NSPLIT; j++) s += __ldcg(&g_partial[r * NSPLIT + j]);
        s += __ldcg(&g_fix[r]);
        lsum += 64.0f + logf(s) - __ldcg(&g_logit[r]);   // -logp[label]
    }
    #pragma unroll
    for (int o = 16; o; o >>= 1) lsum += __shfl_down_sync(0xffffffffu, lsum, o);
    if ((tid & 31) == 0) sh[tid >> 5] = lsum;
    __syncthreads();
    if (tid < 32) {
        float v = (tid < 8) ? sh[tid] : 0.0f;
        #pragma unroll
        for (int o = 4; o; o >>= 1) v += __shfl_down_sync(0xffffffffu, v, o);
        if (tid == 0) {
            out[0] = v / (float)BQ;
            g_done = 0;                      // fresh counter for next replay
        }
    }
}

// ----------------------------------------------------------------------------
extern "C" void kernel_launch(void* const* d_in, const int* in_sizes, int n_in,
                              void* d_out, int out_size) {
    const float* costh = (const float*)d_in[0];
    const float* eps   = (const float*)d_in[1];
    const int*   lab32 = (const int*)d_in[2];
    int C = in_sizes[0] / BQ;        // 100000

    stats_kernel<<<1, BQ>>>(costh, eps, lab32, C);
    main_kernel<<<GRID, NTHR>>>(costh, eps, (float*)d_out, C);
}